// round 2
// baseline (speedup 1.0000x reference)
#include <cuda_runtime.h>
#include <cuda_bf16.h>
#include <mma.h>
#include <cstdint>

using namespace nvcuda;

// ---------------------------------------------------------------------------
// Problem constants (fixed shapes)
// ---------------------------------------------------------------------------
#define NT_TOKENS 16384          // B*S = 4*4096
#define D_DIM     2048
#define F_DIM     2048
#define NE        4
#define VOCAB_SZ  100000
#define TPE       (VOCAB_SZ / NE)   // 25000

// GEMM tiling
#define BM 128
#define BN 128
#define BK 16
#define WM 64
#define WN 32
#define THREADS 256              // 8 warps: 2 (m) x 4 (n)
#define KT (2048 / BK)           // 128 k-tiles (K is 2048 for all three GEMMs)

#define PADTOT (NT_TOKENS + NE * BM)   // 16896 padded compact rows

// ---------------------------------------------------------------------------
// Static device scratch (allocation-free rule: __device__ globals)
// ---------------------------------------------------------------------------
__device__ int   g_count[NE];
__device__ int   g_fill[NE];
__device__ int   g_poff[NE + 1];           // BM-aligned exclusive scan
__device__ int   g_perm[PADTOT];           // compact padded row -> token index
__device__ int   g_shift;                  // 0: token_ids are int32; 1: int64
__device__ float g_G[(size_t)PADTOT * F_DIM];   // silu(gate) ; reused as Ybuf
__device__ float g_H[(size_t)PADTOT * F_DIM];   // silu(gate)*up

// ---------------------------------------------------------------------------
// Routing kernels (dtype-agnostic: token i = tok32[i << g_shift])
// ---------------------------------------------------------------------------
__device__ __forceinline__ int expert_of_i32(int t) {
    if (t < 0) t = 0;
    if (t > VOCAB_SZ - 1) t = VOCAB_SZ - 1;
    int e = t / TPE;
    return e > NE - 1 ? NE - 1 : e;
}

// Detect physical dtype of token buffer. If the data is really int64 (ids
// < 2^31), every high 32-bit word is zero. If it is int32, the "high word"
// of pair i is token (2i+1), which is nonzero with overwhelming probability
// across 256 samples. Also zero the counters here.
__global__ void k_init_detect(const int* __restrict__ tok32) {
    __shared__ int any_nonzero;
    if (threadIdx.x == 0) any_nonzero = 0;
    if (threadIdx.x < NE) { g_count[threadIdx.x] = 0; g_fill[threadIdx.x] = 0; }
    __syncthreads();
    // 256 threads, one int64-interpretation each (reads within 16384 int32s)
    if (tok32[2 * threadIdx.x + 1] != 0) any_nonzero = 1;
    __syncthreads();
    if (threadIdx.x == 0) g_shift = any_nonzero ? 0 : 1;  // nonzero hi => int32
}

__global__ void k_count(const int* __restrict__ tok32) {
    int i = blockIdx.x * blockDim.x + threadIdx.x;
    if (i < NT_TOKENS) {
        int t = tok32[(size_t)i << g_shift];   // low word (LE) or int32 element
        atomicAdd(&g_count[expert_of_i32(t)], 1);
    }
}

__global__ void k_scan() {
    int acc = 0;
    for (int e = 0; e < NE; ++e) {
        g_poff[e] = acc;
        acc += (g_count[e] + BM - 1) / BM * BM;
    }
    g_poff[NE] = acc;
}

__global__ void k_build_perm(const int* __restrict__ tok32) {
    int i = blockIdx.x * blockDim.x + threadIdx.x;
    if (i < NT_TOKENS) {
        int t = tok32[(size_t)i << g_shift];
        int e = expert_of_i32(t);
        int pos = g_poff[e] + atomicAdd(&g_fill[e], 1);
        g_perm[pos] = i;
    }
}

// ---------------------------------------------------------------------------
// cp.async helpers
// ---------------------------------------------------------------------------
__device__ __forceinline__ void cp_async16(void* smem, const void* gmem) {
    uint32_t s = (uint32_t)__cvta_generic_to_shared(smem);
    asm volatile("cp.async.cg.shared.global [%0], [%1], 16;\n" :: "r"(s), "l"(gmem));
}
__device__ __forceinline__ void cp_commit() {
    asm volatile("cp.async.commit_group;\n");
}
__device__ __forceinline__ void cp_wait1() {
    asm volatile("cp.async.wait_group 1;\n" ::: "memory");
}
__device__ __forceinline__ void cp_wait0() {
    asm volatile("cp.async.wait_group 0;\n" ::: "memory");
}

// ---------------------------------------------------------------------------
// Grouped GEMM: C[M,N] = A[M,K] * W[N,K]^T  (both K-contiguous)
//
// MODE 0 (gate): A = X rows gathered via g_perm; W = Wg[e];  G <- silu(acc)
// MODE 1 (up):   A = X rows gathered via g_perm; W = Wu[e];  H <- acc * G
// MODE 2 (down): A = g_H compact rows;           W = Wd[e];  Ybuf(g_G) <- acc
//
// Per-expert rows padded to BM multiples; pad rows load zeros -> acc 0 ->
// G/H/Y pad rows are exact zeros; never scattered to output.
// ---------------------------------------------------------------------------
template <int MODE>
__global__ __launch_bounds__(THREADS)
void gemm_kernel(const float* __restrict__ X, const float* __restrict__ Wall) {
    const int e   = blockIdx.z;
    const int cnt = g_count[e];
    const int m0  = blockIdx.y * BM;
    if (m0 >= cnt) return;
    const int n0   = blockIdx.x * BN;
    const int base = g_poff[e];

    const float* __restrict__ W = Wall + (size_t)e * F_DIM * D_DIM;  // [2048, 2048]

    __shared__ __align__(16) float As[2][BM][BK];
    __shared__ __align__(16) float Bs[2][BN][BK];

    const int tid = threadIdx.x;

    // Per-thread load mapping: 512 float4 per 128x16 tile -> 2 per thread.
    const float* aptr[2];
    const float* bptr[2];
    bool avalid[2];
    int  arow[2], acol[2];

#pragma unroll
    for (int j = 0; j < 2; ++j) {
        int idx = tid + j * THREADS;    // 0..511
        int r   = idx >> 2;             // 0..127
        int c4  = idx & 3;              // 0..3
        arow[j] = r; acol[j] = c4 * 4;
        if (MODE < 2) {
            bool v = (m0 + r) < cnt;
            avalid[j] = v;
            int grow = v ? g_perm[base + m0 + r] : 0;
            aptr[j] = X + (size_t)grow * D_DIM + c4 * 4;
        } else {
            avalid[j] = true;  // padded region, in-bounds, contains zeros
            aptr[j] = g_H + (size_t)(base + m0 + r) * F_DIM + c4 * 4;
        }
        bptr[j] = W + (size_t)(n0 + r) * 2048 + c4 * 4;
    }

    // Zero-fill invalid A rows once (both buffers); cp.async never touches them.
    if (MODE < 2) {
#pragma unroll
        for (int j = 0; j < 2; ++j) {
            if (!avalid[j]) {
                float4 z = make_float4(0.f, 0.f, 0.f, 0.f);
                *(float4*)&As[0][arow[j]][acol[j]] = z;
                *(float4*)&As[1][arow[j]][acol[j]] = z;
            }
        }
    }

    // Accumulators: warp tile 64x32 = 4x2 fragments of 16x16
    const int wid = tid >> 5;
    const int wm  = (wid >> 2) * WM;   // 0 or 64
    const int wn  = (wid & 3) * WN;    // 0,32,64,96

    wmma::fragment<wmma::accumulator, 16, 16, 8, float> acc[4][2];
#pragma unroll
    for (int i = 0; i < 4; ++i)
#pragma unroll
        for (int j = 0; j < 2; ++j)
            wmma::fill_fragment(acc[i][j], 0.0f);

    // ---- prologue: stage 0 ----
#pragma unroll
    for (int j = 0; j < 2; ++j) {
        if (avalid[j]) cp_async16(&As[0][arow[j]][acol[j]], aptr[j]);
        cp_async16(&Bs[0][arow[j]][acol[j]], bptr[j]);
    }
    cp_commit();

    // ---- main loop, double-buffered ----
    for (int kt = 0; kt < KT; ++kt) {
        const int cur = kt & 1;
        if (kt + 1 < KT) {
            const int nxt = cur ^ 1;
            const int k0  = (kt + 1) * BK;
#pragma unroll
            for (int j = 0; j < 2; ++j) {
                if (avalid[j]) cp_async16(&As[nxt][arow[j]][acol[j]], aptr[j] + k0);
                cp_async16(&Bs[nxt][arow[j]][acol[j]], bptr[j] + k0);
            }
            cp_commit();
            cp_wait1();
        } else {
            cp_wait0();
        }
        __syncthreads();

#pragma unroll
        for (int ks = 0; ks < 2; ++ks) {
            const int kk = ks * 8;
            wmma::fragment<wmma::matrix_a, 16, 16, 8, wmma::precision::tf32,
                           wmma::row_major> af[4];
            wmma::fragment<wmma::matrix_b, 16, 16, 8, wmma::precision::tf32,
                           wmma::col_major> bf[2];
#pragma unroll
            for (int i = 0; i < 4; ++i) {
                wmma::load_matrix_sync(af[i], &As[cur][wm + i * 16][kk], BK);
#pragma unroll
                for (int t = 0; t < af[i].num_elements; ++t)
                    af[i].x[t] = wmma::__float_to_tf32(af[i].x[t]);
            }
#pragma unroll
            for (int j = 0; j < 2; ++j) {
                wmma::load_matrix_sync(bf[j], &Bs[cur][wn + j * 16][kk], BK);
#pragma unroll
                for (int t = 0; t < bf[j].num_elements; ++t)
                    bf[j].x[t] = wmma::__float_to_tf32(bf[j].x[t]);
            }
#pragma unroll
            for (int i = 0; i < 4; ++i)
#pragma unroll
                for (int j = 0; j < 2; ++j)
                    wmma::mma_sync(acc[i][j], af[i], bf[j], acc[i][j]);
        }
        __syncthreads();
    }

    // ---- epilogue ----
    const size_t row_base = (size_t)(base + m0 + wm);
#pragma unroll
    for (int i = 0; i < 4; ++i) {
#pragma unroll
        for (int j = 0; j < 2; ++j) {
            const size_t off = (row_base + i * 16) * (size_t)F_DIM + (n0 + wn + j * 16);
            if (MODE == 0) {
                // silu, store to G
#pragma unroll
                for (int t = 0; t < acc[i][j].num_elements; ++t) {
                    float v = acc[i][j].x[t];
                    acc[i][j].x[t] = v / (1.0f + expf(-v));
                }
                wmma::store_matrix_sync(&g_G[off], acc[i][j], F_DIM, wmma::mem_row_major);
            } else if (MODE == 1) {
                // elementwise multiply by G (load into matching accum fragment)
                wmma::fragment<wmma::accumulator, 16, 16, 8, float> gf;
                wmma::load_matrix_sync(gf, &g_G[off], F_DIM, wmma::mem_row_major);
#pragma unroll
                for (int t = 0; t < acc[i][j].num_elements; ++t)
                    acc[i][j].x[t] *= gf.x[t];
                wmma::store_matrix_sync(&g_H[off], acc[i][j], F_DIM, wmma::mem_row_major);
            } else {
                // down proj -> Ybuf (reuse g_G)
                wmma::store_matrix_sync(&g_G[off], acc[i][j], F_DIM, wmma::mem_row_major);
            }
        }
    }
}

// ---------------------------------------------------------------------------
// Final scatter: compact Ybuf rows -> out[token]
// ---------------------------------------------------------------------------
__global__ void k_scatter_out(float* __restrict__ out) {
    const int p = blockIdx.x;                 // padded compact row
    if (p >= g_poff[NE]) return;
    int e = 0;
    while (e < NE - 1 && p >= g_poff[e + 1]) ++e;
    const int local = p - g_poff[e];
    if (local >= g_count[e]) return;          // pad row
    const int t = g_perm[p];
    const float4* __restrict__ src = (const float4*)(g_G + (size_t)p * D_DIM);
    float4* __restrict__ dst = (float4*)(out + (size_t)t * D_DIM);
    for (int i = threadIdx.x; i < D_DIM / 4; i += blockDim.x)
        dst[i] = src[i];
}

// ---------------------------------------------------------------------------
// Entry point
// ---------------------------------------------------------------------------
extern "C" void kernel_launch(void* const* d_in, const int* in_sizes, int n_in,
                              void* d_out, int out_size) {
    const float* X     = (const float*)d_in[0];
    const int*   tok32 = (const int*)d_in[1];   // physical view; g_shift handles dtype
    const float* Wg    = (const float*)d_in[2];
    const float* Wu    = (const float*)d_in[3];
    const float* Wd    = (const float*)d_in[4];
    float*       out   = (float*)d_out;

    // routing
    k_init_detect<<<1, 256>>>(tok32);
    k_count<<<NT_TOKENS / 256, 256>>>(tok32);
    k_scan<<<1, 1>>>();
    k_build_perm<<<NT_TOKENS / 256, 256>>>(tok32);

    // grouped GEMMs: grid covers worst case; blocks with m0 >= count[e] exit
    dim3 grid(F_DIM / BN, NT_TOKENS / BM, NE);   // (16, 128, 4)
    gemm_kernel<0><<<grid, THREADS>>>(X, Wg);
    gemm_kernel<1><<<grid, THREADS>>>(X, Wu);
    gemm_kernel<2><<<grid, THREADS>>>(nullptr, Wd);

    // scatter to output token order
    k_scatter_out<<<PADTOT, 128>>>(out);
}

// round 8
// speedup vs baseline: 5.7335x; 5.7335x over previous
#include <cuda_runtime.h>
#include <cuda_fp16.h>
#include <cstdint>

// ---------------------------------------------------------------------------
// Problem constants
// ---------------------------------------------------------------------------
#define NT_TOKENS 16384
#define D_DIM     2048
#define F_DIM     2048
#define NE        4
#define VOCAB_SZ  100000
#define TPE       (VOCAB_SZ / NE)

#define BM        128
#define PADTOT    (NT_TOKENS + NE * BM)   // 16896
#define MT_MAX    (PADTOT / BM)           // 132
#define KTILES    32                      // 2048 / 64

// ---------------------------------------------------------------------------
// Device scratch (allocation-free rule: __device__ globals)
// ---------------------------------------------------------------------------
__device__ int    g_count[NE];
__device__ int    g_fill[NE];
__device__ int    g_poff[NE + 1];
__device__ int    g_perm[PADTOT];
__device__ int    g_shift;
__device__ __half hX [(size_t)NT_TOKENS * D_DIM];
__device__ __half hWg[(size_t)NE * F_DIM * D_DIM];
__device__ __half hWu[(size_t)NE * F_DIM * D_DIM];
__device__ __half hWd[(size_t)NE * D_DIM * F_DIM];
__device__ __half hH [(size_t)PADTOT * F_DIM];

// ---------------------------------------------------------------------------
// Routing (dtype-agnostic token read: token i = tok32[i << g_shift])
// ---------------------------------------------------------------------------
__device__ __forceinline__ int expert_of_i32(int t) {
    if (t < 0) t = 0;
    if (t > VOCAB_SZ - 1) t = VOCAB_SZ - 1;
    int e = t / TPE;
    return e > NE - 1 ? NE - 1 : e;
}

__global__ void k_init_detect(const int* __restrict__ tok32) {
    __shared__ int any_nonzero;
    if (threadIdx.x == 0) any_nonzero = 0;
    if (threadIdx.x < NE) { g_count[threadIdx.x] = 0; g_fill[threadIdx.x] = 0; }
    __syncthreads();
    if (tok32[2 * threadIdx.x + 1] != 0) any_nonzero = 1;
    __syncthreads();
    if (threadIdx.x == 0) g_shift = any_nonzero ? 0 : 1;
}

__global__ void k_count(const int* __restrict__ tok32) {
    int i = blockIdx.x * blockDim.x + threadIdx.x;
    if (i < NT_TOKENS)
        atomicAdd(&g_count[expert_of_i32(tok32[(size_t)i << g_shift])], 1);
}

__global__ void k_scan() {
    int acc = 0;
    for (int e = 0; e < NE; ++e) {
        g_poff[e] = acc;
        acc += (g_count[e] + BM - 1) / BM * BM;
    }
    g_poff[NE] = acc;
}

__global__ void k_build_perm(const int* __restrict__ tok32) {
    int i = blockIdx.x * blockDim.x + threadIdx.x;
    if (i < NT_TOKENS) {
        int e = expert_of_i32(tok32[(size_t)i << g_shift]);
        g_perm[g_poff[e] + atomicAdd(&g_fill[e], 1)] = i;
    }
}

// ---------------------------------------------------------------------------
// fp32 -> fp16 conversion (vectorized, 8 elems/thread)
// ---------------------------------------------------------------------------
__global__ void k_cvt(const float* __restrict__ src, __half* __restrict__ dst, int n) {
    int i = (blockIdx.x * blockDim.x + threadIdx.x) * 8;
    if (i < n) {
        float4 f0 = *(const float4*)(src + i);
        float4 f1 = *(const float4*)(src + i + 4);
        __half2 h[4];
        h[0] = __floats2half2_rn(f0.x, f0.y);
        h[1] = __floats2half2_rn(f0.z, f0.w);
        h[2] = __floats2half2_rn(f1.x, f1.y);
        h[3] = __floats2half2_rn(f1.z, f1.w);
        *(uint4*)(dst + i) = *(uint4*)h;
    }
}

// ---------------------------------------------------------------------------
// PTX helpers (sm_100-baseline legal: cp.async, ldmatrix, mma.sync)
// ---------------------------------------------------------------------------
__device__ __forceinline__ void cpa16(uint32_t s, const void* g) {
    asm volatile("cp.async.cg.shared.global [%0], [%1], 16;" :: "r"(s), "l"(g));
}
__device__ __forceinline__ void cpa_commit() {
    asm volatile("cp.async.commit_group;");
}
template <int N> __device__ __forceinline__ void cpa_wait() {
    asm volatile("cp.async.wait_group %0;" :: "n"(N) : "memory");
}
__device__ __forceinline__ void ldm_x4(uint32_t* r, uint32_t addr) {
    asm volatile("ldmatrix.sync.aligned.m8n8.x4.shared.b16 {%0,%1,%2,%3}, [%4];"
                 : "=r"(r[0]), "=r"(r[1]), "=r"(r[2]), "=r"(r[3]) : "r"(addr));
}
__device__ __forceinline__ void mma16816(float* c, const uint32_t* a,
                                         uint32_t b0, uint32_t b1) {
    asm volatile(
        "mma.sync.aligned.m16n8k16.row.col.f32.f16.f16.f32 "
        "{%0,%1,%2,%3}, {%4,%5,%6,%7}, {%8,%9}, {%0,%1,%2,%3};"
        : "+f"(c[0]), "+f"(c[1]), "+f"(c[2]), "+f"(c[3])
        : "r"(a[0]), "r"(a[1]), "r"(a[2]), "r"(a[3]), "r"(b0), "r"(b1));
}

// ---------------------------------------------------------------------------
// GEMM: 512 threads, 16 warps (4m x 4n), CTA tile 128x128, BK=64 fp16,
// 3-stage cp.async ring, SW128 XOR swizzle, conflict-free ldmatrix.
//
// MODE 0 (gate+up fused): A = hX rows gathered via g_perm, B = hWg & hWu;
//                         epilogue hH = silu(g) * u   (fp16)
// MODE 1 (down+scatter):  A = hH compact rows, B = hWd;
//                         epilogue scatter fp32 rows to out[token]
// ---------------------------------------------------------------------------
template <int MODE>
__global__ __launch_bounds__(512, 1)
void k_mlp(float* __restrict__ out) {
    const int e   = blockIdx.z;
    const int cnt = g_count[e];
    const int my  = blockIdx.y;
    if (my * BM >= cnt) return;
    const int n0       = blockIdx.x * 128;
    const int base     = g_poff[e];
    const int rowstart = base + my * BM;

    constexpr int STAGE = (MODE == 0) ? 49152 : 32768;   // A16K + B16K(+B16K)

    extern __shared__ __align__(16) char smem[];
    const uint32_t su = (uint32_t)__cvta_generic_to_shared(smem);

    const int tid = threadIdx.x;
    const int l   = tid & 31;
    const int wid = tid >> 5;
    const int wm  = (wid & 3) * 32;    // warp m-offset
    const int wn  = (wid >> 2) * 32;   // warp n-offset

    // ---- cp.async source pointers & smem destinations (2 rows per thread) ----
    const int c = tid & 7;             // 16B chunk (8 per 128B row)
    const char* aG[2];
    const char* b1G[2];
    const char* b2G[2];
    uint32_t dstA[2], dstB[2];

#pragma unroll
    for (int t = 0; t < 2; ++t) {
        const int row = (tid >> 3) + t * 64;           // 0..127
        const uint32_t sw = (uint32_t)((c ^ (row & 7)) * 16);
        dstA[t] = (uint32_t)(row * 128) + sw;
        dstB[t] = dstA[t];
        if (MODE == 0) {
            const int grow = (my * BM + row) < cnt ? g_perm[rowstart + row] : 0;
            aG[t]  = (const char*)hX + (size_t)grow * (D_DIM * 2) + c * 16;
            const size_t wb = ((size_t)e * F_DIM * D_DIM + (size_t)(n0 + row) * D_DIM) * 2;
            b1G[t] = (const char*)hWg + wb + c * 16;
            b2G[t] = (const char*)hWu + wb + c * 16;
        } else {
            aG[t]  = (const char*)hH + (size_t)(rowstart + row) * (F_DIM * 2) + c * 16;
            const size_t wb = ((size_t)e * D_DIM * F_DIM + (size_t)(n0 + row) * F_DIM) * 2;
            b1G[t] = (const char*)hWd + wb + c * 16;
            b2G[t] = nullptr;
        }
    }

#define LOADST(slot, kt)                                                     \
    do {                                                                     \
        const uint32_t sb = su + (uint32_t)(slot) * STAGE;                   \
        const size_t ko = (size_t)(kt) * 128;                                \
        _Pragma("unroll")                                                    \
        for (int t = 0; t < 2; ++t) {                                        \
            cpa16(sb + dstA[t], aG[t] + ko);                                 \
            cpa16(sb + 16384 + dstB[t], b1G[t] + ko);                        \
            if (MODE == 0) cpa16(sb + 32768 + dstB[t], b2G[t] + ko);         \
        }                                                                    \
        cpa_commit();                                                        \
    } while (0)

    // ---- ldmatrix per-lane address components ----
    const int kha = (l >> 4) & 1;                       // A k-half
    const int khb = (l >> 3) & 1;                       // B k-half
    int rowA[2], rowB[2];
#pragma unroll
    for (int mi = 0; mi < 2; ++mi) rowA[mi] = wm + mi * 16 + (l & 15);
#pragma unroll
    for (int bi = 0; bi < 2; ++bi) rowB[bi] = wn + bi * 16 + ((l & 16) ? 8 : 0) + (l & 7);

    // ---- accumulators ----
    float c1[2][4][4];                                  // gate (or down)
    float c2[2][4][4];                                  // up   (MODE 0 only)
#pragma unroll
    for (int mi = 0; mi < 2; ++mi)
#pragma unroll
        for (int nt = 0; nt < 4; ++nt)
#pragma unroll
            for (int k = 0; k < 4; ++k) { c1[mi][nt][k] = 0.f; if (MODE == 0) c2[mi][nt][k] = 0.f; }

    LOADST(0, 0);
    LOADST(1, 1);

    for (int kt = 0; kt < KTILES; ++kt) {
        if (kt == KTILES - 1) cpa_wait<0>(); else cpa_wait<1>();
        __syncthreads();
        if (kt + 2 < KTILES) LOADST((kt + 2) % 3, kt + 2);

        const uint32_t sb = su + (uint32_t)(kt % 3) * STAGE;

#pragma unroll
        for (int ks = 0; ks < 4; ++ks) {
            uint32_t a[2][4];
#pragma unroll
            for (int mi = 0; mi < 2; ++mi)
                ldm_x4(a[mi], sb + (uint32_t)(rowA[mi] * 128) +
                              (uint32_t)((((ks * 2 + kha) ^ (rowA[mi] & 7)) << 4)));
            uint32_t b1[2][4];
#pragma unroll
            for (int bi = 0; bi < 2; ++bi)
                ldm_x4(b1[bi], sb + 16384 + (uint32_t)(rowB[bi] * 128) +
                               (uint32_t)((((ks * 2 + khb) ^ (rowB[bi] & 7)) << 4)));
#pragma unroll
            for (int mi = 0; mi < 2; ++mi)
#pragma unroll
                for (int nt = 0; nt < 4; ++nt)
                    mma16816(c1[mi][nt], a[mi], b1[nt >> 1][(nt & 1) * 2],
                             b1[nt >> 1][(nt & 1) * 2 + 1]);
            if (MODE == 0) {
                uint32_t b2[2][4];
#pragma unroll
                for (int bi = 0; bi < 2; ++bi)
                    ldm_x4(b2[bi], sb + 32768 + (uint32_t)(rowB[bi] * 128) +
                                   (uint32_t)((((ks * 2 + khb) ^ (rowB[bi] & 7)) << 4)));
#pragma unroll
                for (int mi = 0; mi < 2; ++mi)
#pragma unroll
                    for (int nt = 0; nt < 4; ++nt)
                        mma16816(c2[mi][nt], a[mi], b2[nt >> 1][(nt & 1) * 2],
                                 b2[nt >> 1][(nt & 1) * 2 + 1]);
            }
        }
        __syncthreads();
    }

    // ---- epilogue ----
    const int g   = l >> 2;
    const int tig = l & 3;
    const int colbase = n0 + wn + tig * 2;

#pragma unroll
    for (int mi = 0; mi < 2; ++mi) {
#pragma unroll
        for (int h = 0; h < 2; ++h) {
            const int row_local = wm + mi * 16 + h * 8 + g;
            const int p = rowstart + row_local;
            if (MODE == 0) {
                __half* dst = hH + (size_t)p * F_DIM + colbase;
#pragma unroll
                for (int nt = 0; nt < 4; ++nt) {
                    float gv0 = c1[mi][nt][h * 2],     uv0 = c2[mi][nt][h * 2];
                    float gv1 = c1[mi][nt][h * 2 + 1], uv1 = c2[mi][nt][h * 2 + 1];
                    float v0 = (gv0 / (1.0f + __expf(-gv0))) * uv0;
                    float v1 = (gv1 / (1.0f + __expf(-gv1))) * uv1;
                    *(__half2*)(dst + nt * 8) = __floats2half2_rn(v0, v1);
                }
            } else {
                const bool valid = (my * BM + row_local) < cnt;
                if (valid) {
                    const int tok = g_perm[p];
                    float* dst = out + (size_t)tok * D_DIM + colbase;
#pragma unroll
                    for (int nt = 0; nt < 4; ++nt)
                        *(float2*)(dst + nt * 8) =
                            make_float2(c1[mi][nt][h * 2], c1[mi][nt][h * 2 + 1]);
                }
            }
        }
    }
}

// ---------------------------------------------------------------------------
// Entry
// ---------------------------------------------------------------------------
extern "C" void kernel_launch(void* const* d_in, const int* in_sizes, int n_in,
                              void* d_out, int out_size) {
    const float* X     = (const float*)d_in[0];
    const int*   tok32 = (const int*)d_in[1];
    const float* Wg    = (const float*)d_in[2];
    const float* Wu    = (const float*)d_in[3];
    const float* Wd    = (const float*)d_in[4];
    float*       out   = (float*)d_out;

    static bool attr_done = false;
    if (!attr_done) {
        cudaFuncSetAttribute(k_mlp<0>, cudaFuncAttributeMaxDynamicSharedMemorySize, 3 * 49152);
        cudaFuncSetAttribute(k_mlp<1>, cudaFuncAttributeMaxDynamicSharedMemorySize, 3 * 32768);
        attr_done = true;
    }

    // routing
    k_init_detect<<<1, 256>>>(tok32);
    k_count<<<NT_TOKENS / 256, 256>>>(tok32);
    k_scan<<<1, 1>>>();
    k_build_perm<<<NT_TOKENS / 256, 256>>>(tok32);

    // fp32 -> fp16 conversion
    __half *dX, *dWg, *dWu, *dWd;
    cudaGetSymbolAddress((void**)&dX,  hX);
    cudaGetSymbolAddress((void**)&dWg, hWg);
    cudaGetSymbolAddress((void**)&dWu, hWu);
    cudaGetSymbolAddress((void**)&dWd, hWd);
    const int nX = NT_TOKENS * D_DIM;                    // 33.6M
    const int nW = NE * F_DIM * D_DIM;                   // 16.8M
    k_cvt<<<nX / (256 * 8), 256>>>(X, dX, nX);
    k_cvt<<<nW / (256 * 8), 256>>>(Wg, dWg, nW);
    k_cvt<<<nW / (256 * 8), 256>>>(Wu, dWu, nW);
    k_cvt<<<nW / (256 * 8), 256>>>(Wd, dWd, nW);

    // GEMMs
    dim3 grid(16, MT_MAX, NE);   // (2048/128, 132, 4)
    k_mlp<0><<<grid, 512, 3 * 49152>>>(nullptr);
    k_mlp<1><<<grid, 512, 3 * 32768>>>(out);
}

// round 9
// speedup vs baseline: 6.6346x; 1.1572x over previous
#include <cuda_runtime.h>
#include <cuda_fp16.h>
#include <cstdint>

// ---------------------------------------------------------------------------
// Problem constants
// ---------------------------------------------------------------------------
#define NT_TOKENS 16384
#define D_DIM     2048
#define F_DIM     2048
#define NE        4
#define VOCAB_SZ  100000
#define TPE       (VOCAB_SZ / NE)

#define BM        128
#define BN        64
#define PADTOT    (NT_TOKENS + NE * BM)   // 16896
#define MT_MAX    (PADTOT / BM)           // 132
#define KTILES    32                      // 2048 / 64

// ---------------------------------------------------------------------------
// Device scratch (allocation-free rule: __device__ globals)
// ---------------------------------------------------------------------------
__device__ int    g_count[NE];
__device__ int    g_fill[NE];
__device__ int    g_perm[PADTOT];
__device__ __half hX [(size_t)NT_TOKENS * D_DIM];
__device__ __half hWg[(size_t)NE * F_DIM * D_DIM];
__device__ __half hWu[(size_t)NE * F_DIM * D_DIM];
__device__ __half hWd[(size_t)NE * D_DIM * F_DIM];
__device__ __half hH [(size_t)PADTOT * F_DIM];

// ---------------------------------------------------------------------------
// Helpers
// ---------------------------------------------------------------------------
__device__ __forceinline__ int expert_of_i32(int t) {
    if (t < 0) t = 0;
    if (t > VOCAB_SZ - 1) t = VOCAB_SZ - 1;
    int e = t / TPE;
    return e > NE - 1 ? NE - 1 : e;
}

// Per-block dtype detect: token_ids declared int64 but may physically be
// int32 (JAX x64 disabled). If int64 (ids < 2^31), every high word is 0.
// Block-local, deterministic, no extra kernel launch. Requires blockDim=256.
__device__ __forceinline__ int detect_shift(const int* __restrict__ tok32,
                                            int* smem_flag) {
    if (threadIdx.x == 0) *smem_flag = 0;
    __syncthreads();
    if (tok32[2 * threadIdx.x + 1] != 0) *smem_flag = 1;
    __syncthreads();
    return *smem_flag ? 0 : 1;   // nonzero high word => physically int32
}

// ---------------------------------------------------------------------------
// Kernel 1: fp32->fp16 conversion of X + 3 weights, plus counter zeroing.
// grid = (16384, 4): y=0 -> X (16384 blocks), y=1..3 -> weights (8192 blocks).
// ---------------------------------------------------------------------------
__global__ void k_cvt_all(const float* __restrict__ X, const float* __restrict__ Wg,
                          const float* __restrict__ Wu, const float* __restrict__ Wd) {
    if (blockIdx.x == 0 && blockIdx.y == 0 && threadIdx.x < NE) {
        g_count[threadIdx.x] = 0;
        g_fill[threadIdx.x]  = 0;
    }
    const float* src;
    __half* dst;
    int n;
    switch (blockIdx.y) {
        case 0: src = X;  dst = hX;  n = NT_TOKENS * D_DIM; break;
        case 1: src = Wg; dst = hWg; n = NE * F_DIM * D_DIM; break;
        case 2: src = Wu; dst = hWu; n = NE * F_DIM * D_DIM; break;
        default: src = Wd; dst = hWd; n = NE * D_DIM * F_DIM; break;
    }
    int i = (blockIdx.x * blockDim.x + threadIdx.x) * 8;
    if (i < n) {
        float4 f0 = *(const float4*)(src + i);
        float4 f1 = *(const float4*)(src + i + 4);
        __half2 h[4];
        h[0] = __floats2half2_rn(f0.x, f0.y);
        h[1] = __floats2half2_rn(f0.z, f0.w);
        h[2] = __floats2half2_rn(f1.x, f1.y);
        h[3] = __floats2half2_rn(f1.z, f1.w);
        *(uint4*)(dst + i) = *(uint4*)h;
    }
}

// ---------------------------------------------------------------------------
// Kernel 2: count tokens per expert (inline dtype detect)
// ---------------------------------------------------------------------------
__global__ void k_count(const int* __restrict__ tok32) {
    __shared__ int flag;
    const int shift = detect_shift(tok32, &flag);
    int i = blockIdx.x * blockDim.x + threadIdx.x;
    if (i < NT_TOKENS)
        atomicAdd(&g_count[expert_of_i32(tok32[(size_t)i << shift])], 1);
}

// ---------------------------------------------------------------------------
// Kernel 3: build permutation (inline detect + local BM-aligned prefix scan)
// ---------------------------------------------------------------------------
__global__ void k_build_perm(const int* __restrict__ tok32) {
    __shared__ int flag;
    const int shift = detect_shift(tok32, &flag);
    int i = blockIdx.x * blockDim.x + threadIdx.x;
    if (i < NT_TOKENS) {
        int t = tok32[(size_t)i << shift];
        int e = expert_of_i32(t);
        int poff = 0;
#pragma unroll
        for (int k = 0; k < NE; ++k)
            if (k < e) poff += (g_count[k] + BM - 1) / BM * BM;
        g_perm[poff + atomicAdd(&g_fill[e], 1)] = i;
    }
}

// ---------------------------------------------------------------------------
// PTX helpers (sm_100-baseline legal)
// ---------------------------------------------------------------------------
__device__ __forceinline__ void cpa16(uint32_t s, const void* g) {
    asm volatile("cp.async.cg.shared.global [%0], [%1], 16;" :: "r"(s), "l"(g));
}
__device__ __forceinline__ void cpa_commit() {
    asm volatile("cp.async.commit_group;");
}
template <int N> __device__ __forceinline__ void cpa_wait() {
    asm volatile("cp.async.wait_group %0;" :: "n"(N) : "memory");
}
__device__ __forceinline__ void ldm_x4(uint32_t* r, uint32_t addr) {
    asm volatile("ldmatrix.sync.aligned.m8n8.x4.shared.b16 {%0,%1,%2,%3}, [%4];"
                 : "=r"(r[0]), "=r"(r[1]), "=r"(r[2]), "=r"(r[3]) : "r"(addr));
}
__device__ __forceinline__ void mma16816(float* c, const uint32_t* a,
                                         uint32_t b0, uint32_t b1) {
    asm volatile(
        "mma.sync.aligned.m16n8k16.row.col.f32.f16.f16.f32 "
        "{%0,%1,%2,%3}, {%4,%5,%6,%7}, {%8,%9}, {%0,%1,%2,%3};"
        : "+f"(c[0]), "+f"(c[1]), "+f"(c[2]), "+f"(c[3])
        : "r"(a[0]), "r"(a[1]), "r"(a[2]), "r"(a[3]), "r"(b0), "r"(b1));
}

// ---------------------------------------------------------------------------
// GEMM: 256 threads (8 warps, 4m x 2n), CTA tile 128x64, BK=64 fp16,
// 3-stage cp.async ring, SW128 XOR swizzle, ONE __syncthreads per k-tile,
// __launch_bounds__(256,2) -> 2 CTAs/SM (16 warps/SM, two sync domains).
//
// MODE 0 (gate+up fused): A = hX rows gathered via g_perm, B = hWg & hWu;
//                         epilogue hH = silu(g) * u   (fp16)
// MODE 1 (down+scatter):  A = hH compact rows, B = hWd;
//                         epilogue scatter fp32 rows to out[token]
// ---------------------------------------------------------------------------
template <int MODE>
__global__ __launch_bounds__(256, 2)
void k_mlp(float* __restrict__ out) {
    const int e   = blockIdx.z;
    const int cnt = g_count[e];
    const int my  = blockIdx.y;
    if (my * BM >= cnt) return;
    const int n0 = blockIdx.x * BN;

    int base = 0;
#pragma unroll
    for (int k = 0; k < NE; ++k)
        if (k < e) base += (g_count[k] + BM - 1) / BM * BM;
    const int rowstart = base + my * BM;

    constexpr int STAGE = (MODE == 0) ? 32768 : 24576;  // A16K + B8K (+B8K)

    extern __shared__ __align__(16) char smem[];
    const uint32_t su = (uint32_t)__cvta_generic_to_shared(smem);

    const int tid = threadIdx.x;
    const int l   = tid & 31;
    const int wid = tid >> 5;
    const int wm  = (wid & 3) * 32;    // warp m-offset: 0,32,64,96
    const int wn  = (wid >> 2) * 32;   // warp n-offset: 0,32

    // ---- cp.async source pointers & smem destinations ----
    // A: 128 rows of 128B -> 1024 chunks -> 4 per thread.
    // B: 64 rows -> 512 chunks -> 2 per thread.
    const int c = tid & 7;             // 16B chunk index within 128B row
    const char* aG[4];
    const char* b1G[2];
    const char* b2G[2];
    uint32_t dstA[4], dstB[2];

#pragma unroll
    for (int t = 0; t < 4; ++t) {
        const int row = (tid >> 3) + t * 32;           // 0..127
        dstA[t] = (uint32_t)(row * 128 + ((c ^ (row & 7)) * 16));
        if (MODE == 0) {
            const int grow = (my * BM + row) < cnt ? g_perm[rowstart + row] : 0;
            aG[t] = (const char*)hX + (size_t)grow * (D_DIM * 2) + c * 16;
        } else {
            aG[t] = (const char*)hH + (size_t)(rowstart + row) * (F_DIM * 2) + c * 16;
        }
    }
#pragma unroll
    for (int t = 0; t < 2; ++t) {
        const int row = (tid >> 3) + t * 32;           // 0..63
        dstB[t] = (uint32_t)(row * 128 + ((c ^ (row & 7)) * 16));
        if (MODE == 0) {
            const size_t wb = ((size_t)e * F_DIM * D_DIM + (size_t)(n0 + row) * D_DIM) * 2;
            b1G[t] = (const char*)hWg + wb + c * 16;
            b2G[t] = (const char*)hWu + wb + c * 16;
        } else {
            const size_t wb = ((size_t)e * D_DIM * F_DIM + (size_t)(n0 + row) * F_DIM) * 2;
            b1G[t] = (const char*)hWd + wb + c * 16;
            b2G[t] = nullptr;
        }
    }

#define LOADST(slot, kt)                                                     \
    do {                                                                     \
        const uint32_t sb = su + (uint32_t)(slot) * STAGE;                   \
        const size_t ko = (size_t)(kt) * 128;                                \
        _Pragma("unroll")                                                    \
        for (int t = 0; t < 4; ++t) cpa16(sb + dstA[t], aG[t] + ko);         \
        _Pragma("unroll")                                                    \
        for (int t = 0; t < 2; ++t) {                                        \
            cpa16(sb + 16384 + dstB[t], b1G[t] + ko);                        \
            if (MODE == 0) cpa16(sb + 24576 + dstB[t], b2G[t] + ko);         \
        }                                                                    \
        cpa_commit();                                                        \
    } while (0)

    // ---- ldmatrix per-lane row indices ----
    const int kha = (l >> 4) & 1;
    const int khb = (l >> 3) & 1;
    int rowA[2], rowB[2];
#pragma unroll
    for (int mi = 0; mi < 2; ++mi) rowA[mi] = wm + mi * 16 + (l & 15);
#pragma unroll
    for (int bi = 0; bi < 2; ++bi) rowB[bi] = wn + bi * 16 + ((l & 16) ? 8 : 0) + (l & 7);

    // ---- accumulators (warp tile 32x32) ----
    float c1[2][4][4];
    float c2[2][4][4];
#pragma unroll
    for (int mi = 0; mi < 2; ++mi)
#pragma unroll
        for (int nt = 0; nt < 4; ++nt)
#pragma unroll
            for (int k = 0; k < 4; ++k) { c1[mi][nt][k] = 0.f; if (MODE == 0) c2[mi][nt][k] = 0.f; }

    LOADST(0, 0);
    LOADST(1, 1);

    // Single-sync ring. Safety argument: LOADST(kt+2) writes slot
    // (kt+2)%3 == (kt-1)%3, whose last readers ran in iteration kt-1;
    // every warp passed the iteration-kt barrier only after finishing
    // iteration kt-1, so the overwrite is ordered. Reads of slot kt%3 are
    // safe because every thread waited for its own group kt before the
    // barrier, and the barrier publishes all cp.async data block-wide.
    for (int kt = 0; kt < KTILES; ++kt) {
        if (kt == KTILES - 1) cpa_wait<0>(); else cpa_wait<1>();
        __syncthreads();
        if (kt + 2 < KTILES) LOADST((kt + 2) % 3, kt + 2);

        const uint32_t sb = su + (uint32_t)(kt % 3) * STAGE;

#pragma unroll
        for (int ks = 0; ks < 4; ++ks) {
            uint32_t a[2][4];
#pragma unroll
            for (int mi = 0; mi < 2; ++mi)
                ldm_x4(a[mi], sb + (uint32_t)(rowA[mi] * 128) +
                              (uint32_t)((((ks * 2 + kha) ^ (rowA[mi] & 7)) << 4)));
            uint32_t b1[2][4];
#pragma unroll
            for (int bi = 0; bi < 2; ++bi)
                ldm_x4(b1[bi], sb + 16384 + (uint32_t)(rowB[bi] * 128) +
                               (uint32_t)((((ks * 2 + khb) ^ (rowB[bi] & 7)) << 4)));
#pragma unroll
            for (int mi = 0; mi < 2; ++mi)
#pragma unroll
                for (int nt = 0; nt < 4; ++nt)
                    mma16816(c1[mi][nt], a[mi], b1[nt >> 1][(nt & 1) * 2],
                             b1[nt >> 1][(nt & 1) * 2 + 1]);
            if (MODE == 0) {
                uint32_t b2[2][4];
#pragma unroll
                for (int bi = 0; bi < 2; ++bi)
                    ldm_x4(b2[bi], sb + 24576 + (uint32_t)(rowB[bi] * 128) +
                                   (uint32_t)((((ks * 2 + khb) ^ (rowB[bi] & 7)) << 4)));
#pragma unroll
                for (int mi = 0; mi < 2; ++mi)
#pragma unroll
                    for (int nt = 0; nt < 4; ++nt)
                        mma16816(c2[mi][nt], a[mi], b2[nt >> 1][(nt & 1) * 2],
                                 b2[nt >> 1][(nt & 1) * 2 + 1]);
            }
        }
    }

    // ---- epilogue ----
    const int g   = l >> 2;
    const int tig = l & 3;
    const int colbase = n0 + wn + tig * 2;

#pragma unroll
    for (int mi = 0; mi < 2; ++mi) {
#pragma unroll
        for (int h = 0; h < 2; ++h) {
            const int row_local = wm + mi * 16 + h * 8 + g;
            const int p = rowstart + row_local;
            if (MODE == 0) {
                __half* dst = hH + (size_t)p * F_DIM + colbase;
#pragma unroll
                for (int nt = 0; nt < 4; ++nt) {
                    float gv0 = c1[mi][nt][h * 2],     uv0 = c2[mi][nt][h * 2];
                    float gv1 = c1[mi][nt][h * 2 + 1], uv1 = c2[mi][nt][h * 2 + 1];
                    float v0 = (gv0 / (1.0f + __expf(-gv0))) * uv0;
                    float v1 = (gv1 / (1.0f + __expf(-gv1))) * uv1;
                    *(__half2*)(dst + nt * 8) = __floats2half2_rn(v0, v1);
                }
            } else {
                if ((my * BM + row_local) < cnt) {
                    const int tok = g_perm[p];
                    float* dst = out + (size_t)tok * D_DIM + colbase;
#pragma unroll
                    for (int nt = 0; nt < 4; ++nt)
                        *(float2*)(dst + nt * 8) =
                            make_float2(c1[mi][nt][h * 2], c1[mi][nt][h * 2 + 1]);
                }
            }
        }
    }
}

// ---------------------------------------------------------------------------
// Entry.  Launch order chosen so the GEMM is launch #4 (ncu has twice
// captured the 4th launch): cvt(1), count(2), perm(3), gateup(4), down(5).
// ---------------------------------------------------------------------------
extern "C" void kernel_launch(void* const* d_in, const int* in_sizes, int n_in,
                              void* d_out, int out_size) {
    const float* X     = (const float*)d_in[0];
    const int*   tok32 = (const int*)d_in[1];
    const float* Wg    = (const float*)d_in[2];
    const float* Wu    = (const float*)d_in[3];
    const float* Wd    = (const float*)d_in[4];
    float*       out   = (float*)d_out;

    static bool attr_done = false;
    if (!attr_done) {
        cudaFuncSetAttribute(k_mlp<0>, cudaFuncAttributeMaxDynamicSharedMemorySize, 3 * 32768);
        cudaFuncSetAttribute(k_mlp<1>, cudaFuncAttributeMaxDynamicSharedMemorySize, 3 * 24576);
        attr_done = true;
    }

    // 1: conversion + counter zeroing (independent of routing)
    dim3 gcvt(NT_TOKENS * D_DIM / (256 * 8), 4);
    k_cvt_all<<<gcvt, 256>>>(X, Wg, Wu, Wd);

    // 2-3: routing
    k_count<<<NT_TOKENS / 256, 256>>>(tok32);
    k_build_perm<<<NT_TOKENS / 256, 256>>>(tok32);

    // 4-5: GEMMs
    dim3 grid(F_DIM / BN, MT_MAX, NE);   // (32, 132, 4)
    k_mlp<0><<<grid, 256, 3 * 32768>>>(nullptr);
    dim3 grid2(D_DIM / BN, MT_MAX, NE);
    k_mlp<1><<<grid2, 256, 3 * 24576>>>(out);
}

// round 10
// speedup vs baseline: 7.0705x; 1.0657x over previous
#include <cuda_runtime.h>
#include <cuda_fp16.h>
#include <cstdint>

// ---------------------------------------------------------------------------
// Problem constants
// ---------------------------------------------------------------------------
#define NT_TOKENS 16384
#define D_DIM     2048
#define F_DIM     2048
#define NE        4
#define VOCAB_SZ  100000
#define TPE       (VOCAB_SZ / NE)

#define BM        128
#define PADTOT    (NT_TOKENS + NE * BM)   // 16896
#define MT_MAX    (PADTOT / BM)           // 132
#define KTILES    32                      // 2048 / 64 fp16

// ---------------------------------------------------------------------------
// Device scratch (allocation-free rule: __device__ globals)
// ---------------------------------------------------------------------------
__device__ int    g_count[NE];
__device__ int    g_fill[NE];
__device__ int    g_perm[PADTOT];
__device__ __half hX [(size_t)NT_TOKENS * D_DIM];
__device__ __half hWg[(size_t)NE * F_DIM * D_DIM];
__device__ __half hWu[(size_t)NE * F_DIM * D_DIM];
__device__ __half hWd[(size_t)NE * D_DIM * F_DIM];
__device__ __half hH [(size_t)PADTOT * F_DIM];

// ---------------------------------------------------------------------------
// Helpers
// ---------------------------------------------------------------------------
__device__ __forceinline__ int expert_of_i32(int t) {
    if (t < 0) t = 0;
    if (t > VOCAB_SZ - 1) t = VOCAB_SZ - 1;
    int e = t / TPE;
    return e > NE - 1 ? NE - 1 : e;
}

// Per-block dtype detect: token_ids declared int64 but may physically be
// int32 (JAX x64 disabled). If int64 (ids < 2^31), every high word is 0.
__device__ __forceinline__ int detect_shift(const int* __restrict__ tok32,
                                            int* smem_flag) {
    if (threadIdx.x == 0) *smem_flag = 0;
    __syncthreads();
    if (tok32[2 * threadIdx.x + 1] != 0) *smem_flag = 1;
    __syncthreads();
    return *smem_flag ? 0 : 1;
}

// ---------------------------------------------------------------------------
// Kernel 1: fp32->fp16 conversion of X + 3 weights, plus counter zeroing.
// ---------------------------------------------------------------------------
__global__ void k_cvt_all(const float* __restrict__ X, const float* __restrict__ Wg,
                          const float* __restrict__ Wu, const float* __restrict__ Wd) {
    if (blockIdx.x == 0 && blockIdx.y == 0 && threadIdx.x < NE) {
        g_count[threadIdx.x] = 0;
        g_fill[threadIdx.x]  = 0;
    }
    const float* src;
    __half* dst;
    int n;
    switch (blockIdx.y) {
        case 0: src = X;  dst = hX;  n = NT_TOKENS * D_DIM; break;
        case 1: src = Wg; dst = hWg; n = NE * F_DIM * D_DIM; break;
        case 2: src = Wu; dst = hWu; n = NE * F_DIM * D_DIM; break;
        default: src = Wd; dst = hWd; n = NE * D_DIM * F_DIM; break;
    }
    int i = (blockIdx.x * blockDim.x + threadIdx.x) * 8;
    if (i < n) {
        float4 f0 = *(const float4*)(src + i);
        float4 f1 = *(const float4*)(src + i + 4);
        __half2 h[4];
        h[0] = __floats2half2_rn(f0.x, f0.y);
        h[1] = __floats2half2_rn(f0.z, f0.w);
        h[2] = __floats2half2_rn(f1.x, f1.y);
        h[3] = __floats2half2_rn(f1.z, f1.w);
        *(uint4*)(dst + i) = *(uint4*)h;
    }
}

// ---------------------------------------------------------------------------
// Kernels 2-3: routing
// ---------------------------------------------------------------------------
__global__ void k_count(const int* __restrict__ tok32) {
    __shared__ int flag;
    const int shift = detect_shift(tok32, &flag);
    int i = blockIdx.x * blockDim.x + threadIdx.x;
    if (i < NT_TOKENS)
        atomicAdd(&g_count[expert_of_i32(tok32[(size_t)i << shift])], 1);
}

__global__ void k_build_perm(const int* __restrict__ tok32) {
    __shared__ int flag;
    const int shift = detect_shift(tok32, &flag);
    int i = blockIdx.x * blockDim.x + threadIdx.x;
    if (i < NT_TOKENS) {
        int t = tok32[(size_t)i << shift];
        int e = expert_of_i32(t);
        int poff = 0;
#pragma unroll
        for (int k = 0; k < NE; ++k)
            if (k < e) poff += (g_count[k] + BM - 1) / BM * BM;
        g_perm[poff + atomicAdd(&g_fill[e], 1)] = i;
    }
}

// ---------------------------------------------------------------------------
// PTX helpers (sm_100-baseline legal)
// ---------------------------------------------------------------------------
__device__ __forceinline__ void cpa16(uint32_t s, const void* g) {
    asm volatile("cp.async.cg.shared.global [%0], [%1], 16;" :: "r"(s), "l"(g));
}
__device__ __forceinline__ void cpa_commit() {
    asm volatile("cp.async.commit_group;");
}
template <int N> __device__ __forceinline__ void cpa_wait() {
    asm volatile("cp.async.wait_group %0;" :: "n"(N) : "memory");
}
__device__ __forceinline__ void ldm_x4(uint32_t* r, uint32_t addr) {
    asm volatile("ldmatrix.sync.aligned.m8n8.x4.shared.b16 {%0,%1,%2,%3}, [%4];"
                 : "=r"(r[0]), "=r"(r[1]), "=r"(r[2]), "=r"(r[3]) : "r"(addr));
}
__device__ __forceinline__ void mma16816(float* c, const uint32_t* a,
                                         uint32_t b0, uint32_t b1) {
    asm volatile(
        "mma.sync.aligned.m16n8k16.row.col.f32.f16.f16.f32 "
        "{%0,%1,%2,%3}, {%4,%5,%6,%7}, {%8,%9}, {%0,%1,%2,%3};"
        : "+f"(c[0]), "+f"(c[1]), "+f"(c[2]), "+f"(c[3])
        : "r"(a[0]), "r"(a[1]), "r"(a[2]), "r"(a[3]), "r"(b0), "r"(b1));
}

// ---------------------------------------------------------------------------
// MODE 0 (gate+up fused): CTA tile 128x64, 8 warps 4m x 2n (warp 32x32 x2),
//   A = hX rows gathered via g_perm, B = hWg & hWu; hH = silu(g)*u.
// MODE 1 (down+scatter):  CTA tile 128x128, 8 warps 4m x 2n (warp 32x64),
//   A = hH compact rows, B = hWd; scatter fp32 rows to out[token].
// Both: BK=64 fp16, 3-stage cp.async ring (stage 32KB), SW128 XOR swizzle,
// one __syncthreads per k-tile, 2 CTAs/SM.
// All global addressing via uint32 byte offsets from a single base (every
// buffer < 4GB) to cut register pressure below the 128-reg 2-CTA cap.
// ---------------------------------------------------------------------------
template <int MODE>
__global__ __launch_bounds__(256, 2)
void k_mlp(float* __restrict__ out) {
    constexpr int BN = (MODE == 0) ? 64 : 128;
    const int e   = blockIdx.z;
    const int cnt = g_count[e];
    const int my  = blockIdx.y;
    if (my * BM >= cnt) return;
    const int n0 = blockIdx.x * BN;

    int base = 0;
#pragma unroll
    for (int k = 0; k < NE; ++k)
        if (k < e) base += (g_count[k] + BM - 1) / BM * BM;
    const int rowstart = base + my * BM;

    constexpr int STAGE = 32768;   // MODE0: A16K+Bg8K+Bu8K ; MODE1: A16K+B16K

    extern __shared__ __align__(16) char smem[];
    const uint32_t su = (uint32_t)__cvta_generic_to_shared(smem);

    const int tid = threadIdx.x;
    const int l   = tid & 31;
    const int wid = tid >> 5;
    const int wm  = (wid & 3) * 32;                    // 0,32,64,96
    const int wn  = (wid >> 2) * (BN / 2);             // MODE0: 0/32, MODE1: 0/64

    // ---- cp.async staging: A 4 chunks/thread; B 2 (MODE0: x2 mats) or 4 ----
    const int c = tid & 7;                             // 16B chunk in 128B row
    const char* const baseA = (MODE == 0) ? (const char*)hX : (const char*)hH;
    const char* const baseB1 = (MODE == 0) ? (const char*)hWg : (const char*)hWd;
    const char* const baseB2 = (const char*)hWu;       // MODE0 only

    uint32_t aOff[4];                                  // byte offsets (<4GB)
    uint32_t bOff[4];                                  // MODE0 uses [0..1]
    uint32_t dstA[4];
#pragma unroll
    for (int t = 0; t < 4; ++t) {
        const int row = (tid >> 3) + t * 32;           // 0..127
        dstA[t] = (uint32_t)(row * 128 + ((c ^ (row & 7)) * 16));
        if (MODE == 0) {
            const int grow = (my * BM + row) < cnt ? g_perm[rowstart + row] : 0;
            aOff[t] = (uint32_t)grow * (D_DIM * 2) + c * 16;
        } else {
            aOff[t] = (uint32_t)(rowstart + row) * (F_DIM * 2) + c * 16;
        }
    }
    constexpr int NBCHUNK = (MODE == 0) ? 2 : 4;
#pragma unroll
    for (int t = 0; t < NBCHUNK; ++t) {
        const int row = (tid >> 3) + t * 32;           // 0..BN-1
        bOff[t] = (uint32_t)((size_t)e * F_DIM * D_DIM * 2) +
                  (uint32_t)(n0 + row) * (D_DIM * 2) + c * 16;
    }

#define LOADST(slot, kt)                                                     \
    do {                                                                     \
        const uint32_t sb = su + (uint32_t)(slot) * STAGE;                   \
        const uint32_t ko = (uint32_t)(kt) * 128;                            \
        _Pragma("unroll")                                                    \
        for (int t = 0; t < 4; ++t) cpa16(sb + dstA[t], baseA + aOff[t] + ko);\
        _Pragma("unroll")                                                    \
        for (int t = 0; t < NBCHUNK; ++t) {                                  \
            cpa16(sb + 16384 + dstA[t], baseB1 + bOff[t] + ko);              \
            if (MODE == 0) cpa16(sb + 24576 + dstA[t], baseB2 + bOff[t] + ko);\
        }                                                                    \
        cpa_commit();                                                        \
    } while (0)

    // ---- ldmatrix per-lane row indices ----
    const int kha = (l >> 4) & 1;
    const int khb = (l >> 3) & 1;
    int rowA[2];
#pragma unroll
    for (int mi = 0; mi < 2; ++mi) rowA[mi] = wm + mi * 16 + (l & 15);
    constexpr int NBF = BN / 32;                       // B ldm_x4 per mat per ks
    int rowB[NBF];
#pragma unroll
    for (int bi = 0; bi < NBF; ++bi)
        rowB[bi] = wn + bi * 16 + ((l & 16) ? 8 : 0) + (l & 7);

    // ---- accumulators ----
    constexpr int NT = BN / 16;                        // n8-tiles per warp half
    float c1[2][NT][4];
    float c2[2][NT][4];                                // MODE0 only
#pragma unroll
    for (int mi = 0; mi < 2; ++mi)
#pragma unroll
        for (int nt = 0; nt < NT; ++nt)
#pragma unroll
            for (int k = 0; k < 4; ++k) { c1[mi][nt][k] = 0.f; if (MODE == 0) c2[mi][nt][k] = 0.f; }

    LOADST(0, 0);
    LOADST(1, 1);

    // Single-sync ring: LOADST(kt+2) writes slot (kt-1)%3 whose readers all
    // finished before the iteration-kt barrier; reads of slot kt%3 are
    // published block-wide by the same barrier after this thread's wait.
    for (int kt = 0; kt < KTILES; ++kt) {
        if (kt == KTILES - 1) cpa_wait<0>(); else cpa_wait<1>();
        __syncthreads();
        if (kt + 2 < KTILES) LOADST((kt + 2) % 3, kt + 2);

        const uint32_t sb = su + (uint32_t)(kt % 3) * STAGE;

#pragma unroll
        for (int ks = 0; ks < 4; ++ks) {
            uint32_t a[2][4];
#pragma unroll
            for (int mi = 0; mi < 2; ++mi)
                ldm_x4(a[mi], sb + (uint32_t)(rowA[mi] * 128) +
                              (uint32_t)((((ks * 2 + kha) ^ (rowA[mi] & 7)) << 4)));
            uint32_t b1[NBF][4];
#pragma unroll
            for (int bi = 0; bi < NBF; ++bi)
                ldm_x4(b1[bi], sb + 16384 + (uint32_t)(rowB[bi] * 128) +
                               (uint32_t)((((ks * 2 + khb) ^ (rowB[bi] & 7)) << 4)));
#pragma unroll
            for (int mi = 0; mi < 2; ++mi)
#pragma unroll
                for (int nt = 0; nt < NT; ++nt)
                    mma16816(c1[mi][nt], a[mi], b1[nt >> 1][(nt & 1) * 2],
                             b1[nt >> 1][(nt & 1) * 2 + 1]);
            if (MODE == 0) {
                uint32_t b2[NBF][4];
#pragma unroll
                for (int bi = 0; bi < NBF; ++bi)
                    ldm_x4(b2[bi], sb + 24576 + (uint32_t)(rowB[bi] * 128) +
                                   (uint32_t)((((ks * 2 + khb) ^ (rowB[bi] & 7)) << 4)));
#pragma unroll
                for (int mi = 0; mi < 2; ++mi)
#pragma unroll
                    for (int nt = 0; nt < NT; ++nt)
                        mma16816(c2[mi][nt], a[mi], b2[nt >> 1][(nt & 1) * 2],
                                 b2[nt >> 1][(nt & 1) * 2 + 1]);
            }
        }
    }

    // ---- epilogue ----
    const int g   = l >> 2;
    const int tig = l & 3;
    const int colbase = n0 + wn + tig * 2;

#pragma unroll
    for (int mi = 0; mi < 2; ++mi) {
#pragma unroll
        for (int h = 0; h < 2; ++h) {
            const int row_local = wm + mi * 16 + h * 8 + g;
            const int p = rowstart + row_local;
            if (MODE == 0) {
                __half* dst = hH + (size_t)p * F_DIM + colbase;
#pragma unroll
                for (int nt = 0; nt < NT; ++nt) {
                    float gv0 = c1[mi][nt][h * 2],     uv0 = c2[mi][nt][h * 2];
                    float gv1 = c1[mi][nt][h * 2 + 1], uv1 = c2[mi][nt][h * 2 + 1];
                    float v0 = (gv0 / (1.0f + __expf(-gv0))) * uv0;
                    float v1 = (gv1 / (1.0f + __expf(-gv1))) * uv1;
                    *(__half2*)(dst + nt * 8) = __floats2half2_rn(v0, v1);
                }
            } else {
                if ((my * BM + row_local) < cnt) {
                    const int tok = g_perm[p];
                    float* dst = out + (size_t)tok * D_DIM + colbase;
#pragma unroll
                    for (int nt = 0; nt < NT; ++nt)
                        *(float2*)(dst + nt * 8) =
                            make_float2(c1[mi][nt][h * 2], c1[mi][nt][h * 2 + 1]);
                }
            }
        }
    }
}

// ---------------------------------------------------------------------------
// Entry.  Launch order keeps the gate+up GEMM as launch #4 (ncu captures it).
// ---------------------------------------------------------------------------
extern "C" void kernel_launch(void* const* d_in, const int* in_sizes, int n_in,
                              void* d_out, int out_size) {
    const float* X     = (const float*)d_in[0];
    const int*   tok32 = (const int*)d_in[1];
    const float* Wg    = (const float*)d_in[2];
    const float* Wu    = (const float*)d_in[3];
    const float* Wd    = (const float*)d_in[4];
    float*       out   = (float*)d_out;

    static bool attr_done = false;
    if (!attr_done) {
        cudaFuncSetAttribute(k_mlp<0>, cudaFuncAttributeMaxDynamicSharedMemorySize, 3 * 32768);
        cudaFuncSetAttribute(k_mlp<1>, cudaFuncAttributeMaxDynamicSharedMemorySize, 3 * 32768);
        attr_done = true;
    }

    // 1: conversion + counter zeroing
    dim3 gcvt(NT_TOKENS * D_DIM / (256 * 8), 4);
    k_cvt_all<<<gcvt, 256>>>(X, Wg, Wu, Wd);

    // 2-3: routing
    k_count<<<NT_TOKENS / 256, 256>>>(tok32);
    k_build_perm<<<NT_TOKENS / 256, 256>>>(tok32);

    // 4: gate+up (CTA 128x64), 5: down+scatter (CTA 128x128)
    dim3 grid0(F_DIM / 64, MT_MAX, NE);    // (32, 132, 4)
    k_mlp<0><<<grid0, 256, 3 * 32768>>>(nullptr);
    dim3 grid1(D_DIM / 128, MT_MAX, NE);   // (16, 132, 4)
    k_mlp<1><<<grid1, 256, 3 * 32768>>>(out);
}

// round 11
// speedup vs baseline: 7.5578x; 1.0689x over previous
#include <cuda_runtime.h>
#include <cuda_fp16.h>
#include <cstdint>

// ---------------------------------------------------------------------------
// Problem constants
// ---------------------------------------------------------------------------
#define NT_TOKENS 16384
#define D_DIM     2048
#define F_DIM     2048
#define NE        4
#define VOCAB_SZ  100000
#define TPE       (VOCAB_SZ / NE)

#define BM        128
#define PADTOT    (NT_TOKENS + NE * BM)   // 16896
#define MT_MAX    (PADTOT / BM)           // 132
#define KTILES    32                      // 2048 / 64 fp16

// ---------------------------------------------------------------------------
// Device scratch (allocation-free rule: __device__ globals)
// ---------------------------------------------------------------------------
__device__ int    g_count[NE];
__device__ int    g_fill[NE];
__device__ int    g_perm[PADTOT];
__device__ __half hX [(size_t)NT_TOKENS * D_DIM];
__device__ __half hWg[(size_t)NE * F_DIM * D_DIM];
__device__ __half hWu[(size_t)NE * F_DIM * D_DIM];
__device__ __half hWd[(size_t)NE * D_DIM * F_DIM];
__device__ __half hH [(size_t)PADTOT * F_DIM];

// ---------------------------------------------------------------------------
// Helpers
// ---------------------------------------------------------------------------
__device__ __forceinline__ int expert_of_i32(int t) {
    if (t < 0) t = 0;
    if (t > VOCAB_SZ - 1) t = VOCAB_SZ - 1;
    int e = t / TPE;
    return e > NE - 1 ? NE - 1 : e;
}

// Per-block dtype detect: token_ids declared int64 but may physically be
// int32 (JAX x64 disabled). If int64 (ids < 2^31), every high word is 0.
__device__ __forceinline__ int detect_shift(const int* __restrict__ tok32,
                                            int* smem_flag) {
    if (threadIdx.x == 0) *smem_flag = 0;
    __syncthreads();
    if (tok32[2 * threadIdx.x + 1] != 0) *smem_flag = 1;
    __syncthreads();
    return *smem_flag ? 0 : 1;
}

// ---------------------------------------------------------------------------
// Kernel 1: fp32->fp16 conversion of X + 3 weights, plus counter zeroing.
// ---------------------------------------------------------------------------
__global__ void k_cvt_all(const float* __restrict__ X, const float* __restrict__ Wg,
                          const float* __restrict__ Wu, const float* __restrict__ Wd) {
    if (blockIdx.x == 0 && blockIdx.y == 0 && threadIdx.x < NE) {
        g_count[threadIdx.x] = 0;
        g_fill[threadIdx.x]  = 0;
    }
    const float* src;
    __half* dst;
    int n;
    switch (blockIdx.y) {
        case 0: src = X;  dst = hX;  n = NT_TOKENS * D_DIM; break;
        case 1: src = Wg; dst = hWg; n = NE * F_DIM * D_DIM; break;
        case 2: src = Wu; dst = hWu; n = NE * F_DIM * D_DIM; break;
        default: src = Wd; dst = hWd; n = NE * D_DIM * F_DIM; break;
    }
    int i = (blockIdx.x * blockDim.x + threadIdx.x) * 8;
    if (i < n) {
        float4 f0 = *(const float4*)(src + i);
        float4 f1 = *(const float4*)(src + i + 4);
        __half2 h[4];
        h[0] = __floats2half2_rn(f0.x, f0.y);
        h[1] = __floats2half2_rn(f0.z, f0.w);
        h[2] = __floats2half2_rn(f1.x, f1.y);
        h[3] = __floats2half2_rn(f1.z, f1.w);
        *(uint4*)(dst + i) = *(uint4*)h;
    }
}

// ---------------------------------------------------------------------------
// Kernels 2-3: routing
// ---------------------------------------------------------------------------
__global__ void k_count(const int* __restrict__ tok32) {
    __shared__ int flag;
    const int shift = detect_shift(tok32, &flag);
    int i = blockIdx.x * blockDim.x + threadIdx.x;
    if (i < NT_TOKENS)
        atomicAdd(&g_count[expert_of_i32(tok32[(size_t)i << shift])], 1);
}

__global__ void k_build_perm(const int* __restrict__ tok32) {
    __shared__ int flag;
    const int shift = detect_shift(tok32, &flag);
    int i = blockIdx.x * blockDim.x + threadIdx.x;
    if (i < NT_TOKENS) {
        int t = tok32[(size_t)i << shift];
        int e = expert_of_i32(t);
        int poff = 0;
#pragma unroll
        for (int k = 0; k < NE; ++k)
            if (k < e) poff += (g_count[k] + BM - 1) / BM * BM;
        g_perm[poff + atomicAdd(&g_fill[e], 1)] = i;
    }
}

// ---------------------------------------------------------------------------
// PTX helpers (sm_100-baseline legal)
// ---------------------------------------------------------------------------
__device__ __forceinline__ void cpa16(uint32_t s, const void* g) {
    asm volatile("cp.async.cg.shared.global [%0], [%1], 16;" :: "r"(s), "l"(g));
}
__device__ __forceinline__ void cpa_commit() {
    asm volatile("cp.async.commit_group;");
}
template <int N> __device__ __forceinline__ void cpa_wait() {
    asm volatile("cp.async.wait_group %0;" :: "n"(N) : "memory");
}
__device__ __forceinline__ void ldm_x4(uint32_t* r, uint32_t addr) {
    asm volatile("ldmatrix.sync.aligned.m8n8.x4.shared.b16 {%0,%1,%2,%3}, [%4];"
                 : "=r"(r[0]), "=r"(r[1]), "=r"(r[2]), "=r"(r[3]) : "r"(addr));
}
__device__ __forceinline__ void mma16816(float* c, const uint32_t* a,
                                         uint32_t b0, uint32_t b1) {
    asm volatile(
        "mma.sync.aligned.m16n8k16.row.col.f32.f16.f16.f32 "
        "{%0,%1,%2,%3}, {%4,%5,%6,%7}, {%8,%9}, {%0,%1,%2,%3};"
        : "+f"(c[0]), "+f"(c[1]), "+f"(c[2]), "+f"(c[3])
        : "r"(a[0]), "r"(a[1]), "r"(a[2]), "r"(a[3]), "r"(b0), "r"(b1));
}

// ---------------------------------------------------------------------------
// MODE 0 (gate+up fused): CTA tile 128x64, 8 warps 4m x 2n.
// MODE 1 (down+scatter):  CTA tile 128x128, 8 warps 4m x 2n (warp 32x64).
// Both: BK=64 fp16, 3-stage cp.async ring (stage 32KB), SW128 XOR swizzle,
// one __syncthreads per k-tile, 2 CTAs/SM.
//
// Inner-loop structure (round-10 change): the prefetch for slot kt+2 is
// issued AFTER the ks=0 fragment-load+MMA batch, so the tensor pipe is busy
// with ks=0 work while LSU/ALU issue the cp.asyncs (tile-boundary bubble
// hidden).  ldmatrix addresses use the XOR-folded identity
//   ((ks*2+kha) ^ (r&7)) << 4  ==  (ks<<5) ^ ((kha^(r&7))<<4)
// so each address is one XOR + one ADD off a precomputed per-fragment const.
// ---------------------------------------------------------------------------
template <int MODE>
__global__ __launch_bounds__(256, 2)
void k_mlp(float* __restrict__ out) {
    constexpr int BN = (MODE == 0) ? 64 : 128;
    const int e   = blockIdx.z;
    const int cnt = g_count[e];
    const int my  = blockIdx.y;
    if (my * BM >= cnt) return;
    const int n0 = blockIdx.x * BN;

    int base = 0;
#pragma unroll
    for (int k = 0; k < NE; ++k)
        if (k < e) base += (g_count[k] + BM - 1) / BM * BM;
    const int rowstart = base + my * BM;

    constexpr int STAGE = 32768;   // MODE0: A16K+Bg8K+Bu8K ; MODE1: A16K+B16K

    extern __shared__ __align__(16) char smem[];
    const uint32_t su = (uint32_t)__cvta_generic_to_shared(smem);

    const int tid = threadIdx.x;
    const int l   = tid & 31;
    const int wid = tid >> 5;
    const int wm  = (wid & 3) * 32;                    // 0,32,64,96
    const int wn  = (wid >> 2) * (BN / 2);             // MODE0: 0/32, MODE1: 0/64

    // ---- cp.async staging: A 4 chunks/thread; B 2 (MODE0: x2 mats) or 4 ----
    const int c = tid & 7;                             // 16B chunk in 128B row
    const char* const baseA = (MODE == 0) ? (const char*)hX : (const char*)hH;
    const char* const baseB1 = (MODE == 0) ? (const char*)hWg : (const char*)hWd;
    const char* const baseB2 = (const char*)hWu;       // MODE0 only

    uint32_t aOff[4];                                  // byte offsets (<4GB)
    uint32_t bOff[4];                                  // MODE0 uses [0..1]
    uint32_t dstA[4];
#pragma unroll
    for (int t = 0; t < 4; ++t) {
        const int row = (tid >> 3) + t * 32;           // 0..127
        dstA[t] = (uint32_t)(row * 128 + ((c ^ (row & 7)) * 16));
        if (MODE == 0) {
            const int grow = (my * BM + row) < cnt ? g_perm[rowstart + row] : 0;
            aOff[t] = (uint32_t)grow * (D_DIM * 2) + c * 16;
        } else {
            aOff[t] = (uint32_t)(rowstart + row) * (F_DIM * 2) + c * 16;
        }
    }
    constexpr int NBCHUNK = (MODE == 0) ? 2 : 4;
#pragma unroll
    for (int t = 0; t < NBCHUNK; ++t) {
        const int row = (tid >> 3) + t * 32;           // 0..BN-1
        bOff[t] = (uint32_t)((size_t)e * F_DIM * D_DIM * 2) +
                  (uint32_t)(n0 + row) * (D_DIM * 2) + c * 16;
    }

#define LOADST(slot, kt)                                                     \
    do {                                                                     \
        const uint32_t sb = su + (uint32_t)(slot) * STAGE;                   \
        const uint32_t ko = (uint32_t)(kt) * 128;                            \
        _Pragma("unroll")                                                    \
        for (int t = 0; t < 4; ++t) cpa16(sb + dstA[t], baseA + aOff[t] + ko);\
        _Pragma("unroll")                                                    \
        for (int t = 0; t < NBCHUNK; ++t) {                                  \
            cpa16(sb + 16384 + dstA[t], baseB1 + bOff[t] + ko);              \
            if (MODE == 0) cpa16(sb + 24576 + dstA[t], baseB2 + bOff[t] + ko);\
        }                                                                    \
        cpa_commit();                                                        \
    } while (0)

    // ---- precomputed ldmatrix fragment constants (region + row*128 + kha part)
    const int kha = (l >> 4) & 1;
    const int khb = (l >> 3) & 1;
    uint32_t pA[2];
#pragma unroll
    for (int mi = 0; mi < 2; ++mi) {
        const int r = wm + mi * 16 + (l & 15);
        pA[mi] = (uint32_t)(r * 128 + ((kha ^ (r & 7)) << 4));
    }
    constexpr int NBF = BN / 32;
    uint32_t pB[NBF];
#pragma unroll
    for (int bi = 0; bi < NBF; ++bi) {
        const int r = wn + bi * 16 + ((l & 16) ? 8 : 0) + (l & 7);
        pB[bi] = (uint32_t)(16384 + r * 128 + ((khb ^ (r & 7)) << 4));
    }

    // ---- accumulators ----
    constexpr int NT = BN / 16;
    float c1[2][NT][4];
    float c2[2][NT][4];                                // MODE0 only
#pragma unroll
    for (int mi = 0; mi < 2; ++mi)
#pragma unroll
        for (int nt = 0; nt < NT; ++nt)
#pragma unroll
            for (int k = 0; k < 4; ++k) { c1[mi][nt][k] = 0.f; if (MODE == 0) c2[mi][nt][k] = 0.f; }

    LOADST(0, 0);
    LOADST(1, 1);

    // One MMA sub-step: fragment loads + MMAs for one ks (16-col k slice).
#define KSTEP(ks)                                                            \
    do {                                                                     \
        const uint32_t kx = (uint32_t)((ks) << 5);                           \
        uint32_t a[2][4];                                                    \
        _Pragma("unroll")                                                    \
        for (int mi = 0; mi < 2; ++mi) ldm_x4(a[mi], sbase + (pA[mi] ^ kx)); \
        uint32_t b1[NBF][4];                                                 \
        _Pragma("unroll")                                                    \
        for (int bi = 0; bi < NBF; ++bi) ldm_x4(b1[bi], sbase + (pB[bi] ^ kx));\
        _Pragma("unroll")                                                    \
        for (int mi = 0; mi < 2; ++mi)                                       \
            _Pragma("unroll")                                                \
            for (int nt = 0; nt < NT; ++nt)                                  \
                mma16816(c1[mi][nt], a[mi], b1[nt >> 1][(nt & 1) * 2],       \
                         b1[nt >> 1][(nt & 1) * 2 + 1]);                     \
        if (MODE == 0) {                                                     \
            uint32_t b2[NBF][4];                                             \
            _Pragma("unroll")                                                \
            for (int bi = 0; bi < NBF; ++bi)                                 \
                ldm_x4(b2[bi], sbase + 8192 + (pB[bi] ^ kx));                \
            _Pragma("unroll")                                                \
            for (int mi = 0; mi < 2; ++mi)                                   \
                _Pragma("unroll")                                            \
                for (int nt = 0; nt < NT; ++nt)                              \
                    mma16816(c2[mi][nt], a[mi], b2[nt >> 1][(nt & 1) * 2],   \
                             b2[nt >> 1][(nt & 1) * 2 + 1]);                 \
        }                                                                    \
    } while (0)

    // Single-sync ring: LOADST(kt+2) writes slot (kt-1)%3 whose readers all
    // finished before this iteration's barrier; reads of slot kt%3 are
    // published block-wide by the same barrier.  The prefetch is issued
    // between ks=0 and ks=1 so cp.async issue overlaps tensor work.
    for (int kt = 0; kt < KTILES; ++kt) {
        if (kt == KTILES - 1) cpa_wait<0>(); else cpa_wait<1>();
        __syncthreads();
        const uint32_t sbase = su + (uint32_t)(kt % 3) * STAGE;

        KSTEP(0);
        if (kt + 2 < KTILES) LOADST((kt + 2) % 3, kt + 2);
        KSTEP(1);
        KSTEP(2);
        KSTEP(3);
    }
#undef KSTEP

    // ---- epilogue ----
    const int g   = l >> 2;
    const int tig = l & 3;
    const int colbase = n0 + wn + tig * 2;

#pragma unroll
    for (int mi = 0; mi < 2; ++mi) {
#pragma unroll
        for (int h = 0; h < 2; ++h) {
            const int row_local = wm + mi * 16 + h * 8 + g;
            const int p = rowstart + row_local;
            if (MODE == 0) {
                __half* dst = hH + (size_t)p * F_DIM + colbase;
#pragma unroll
                for (int nt = 0; nt < NT; ++nt) {
                    float gv0 = c1[mi][nt][h * 2],     uv0 = c2[mi][nt][h * 2];
                    float gv1 = c1[mi][nt][h * 2 + 1], uv1 = c2[mi][nt][h * 2 + 1];
                    float v0 = (gv0 / (1.0f + __expf(-gv0))) * uv0;
                    float v1 = (gv1 / (1.0f + __expf(-gv1))) * uv1;
                    *(__half2*)(dst + nt * 8) = __floats2half2_rn(v0, v1);
                }
            } else {
                if ((my * BM + row_local) < cnt) {
                    const int tok = g_perm[p];
                    float* dst = out + (size_t)tok * D_DIM + colbase;
#pragma unroll
                    for (int nt = 0; nt < NT; ++nt)
                        *(float2*)(dst + nt * 8) =
                            make_float2(c1[mi][nt][h * 2], c1[mi][nt][h * 2 + 1]);
                }
            }
        }
    }
}

// ---------------------------------------------------------------------------
// Entry.  Launch order keeps the gate+up GEMM as launch #4 (ncu captures it).
// ---------------------------------------------------------------------------
extern "C" void kernel_launch(void* const* d_in, const int* in_sizes, int n_in,
                              void* d_out, int out_size) {
    const float* X     = (const float*)d_in[0];
    const int*   tok32 = (const int*)d_in[1];
    const float* Wg    = (const float*)d_in[2];
    const float* Wu    = (const float*)d_in[3];
    const float* Wd    = (const float*)d_in[4];
    float*       out   = (float*)d_out;

    static bool attr_done = false;
    if (!attr_done) {
        cudaFuncSetAttribute(k_mlp<0>, cudaFuncAttributeMaxDynamicSharedMemorySize, 3 * 32768);
        cudaFuncSetAttribute(k_mlp<1>, cudaFuncAttributeMaxDynamicSharedMemorySize, 3 * 32768);
        attr_done = true;
    }

    // 1: conversion + counter zeroing
    dim3 gcvt(NT_TOKENS * D_DIM / (256 * 8), 4);
    k_cvt_all<<<gcvt, 256>>>(X, Wg, Wu, Wd);

    // 2-3: routing
    k_count<<<NT_TOKENS / 256, 256>>>(tok32);
    k_build_perm<<<NT_TOKENS / 256, 256>>>(tok32);

    // 4: gate+up (CTA 128x64), 5: down+scatter (CTA 128x128)
    dim3 grid0(F_DIM / 64, MT_MAX, NE);    // (32, 132, 4)
    k_mlp<0><<<grid0, 256, 3 * 32768>>>(nullptr);
    dim3 grid1(D_DIM / 128, MT_MAX, NE);   // (16, 132, 4)
    k_mlp<1><<<grid1, 256, 3 * 32768>>>(out);
}

// round 12
// speedup vs baseline: 7.7859x; 1.0302x over previous
#include <cuda_runtime.h>
#include <cuda_fp16.h>
#include <cstdint>

// ---------------------------------------------------------------------------
// Problem constants
// ---------------------------------------------------------------------------
#define NT_TOKENS 16384
#define D_DIM     2048
#define F_DIM     2048
#define NE        4
#define VOCAB_SZ  100000
#define TPE       (VOCAB_SZ / NE)

#define BM        128
#define PADTOT    (NT_TOKENS + NE * BM)   // 16896
#define MT_MAX    (PADTOT / BM)           // 132
#define KTILES    32                      // 2048 / 64 fp16

// ---------------------------------------------------------------------------
// Device scratch (allocation-free rule: __device__ globals)
// ---------------------------------------------------------------------------
__device__ int    g_count[NE];
__device__ int    g_perm[PADTOT];
__device__ __half hX [(size_t)NT_TOKENS * D_DIM];
__device__ __half hWg[(size_t)NE * F_DIM * D_DIM];
__device__ __half hWu[(size_t)NE * F_DIM * D_DIM];
__device__ __half hWd[(size_t)NE * D_DIM * F_DIM];
__device__ __half hH [(size_t)PADTOT * F_DIM];

// ---------------------------------------------------------------------------
// Helpers
// ---------------------------------------------------------------------------
__device__ __forceinline__ int expert_of_i32(int t) {
    if (t < 0) t = 0;
    if (t > VOCAB_SZ - 1) t = VOCAB_SZ - 1;
    int e = t / TPE;
    return e > NE - 1 ? NE - 1 : e;
}

// Per-block dtype detect: token_ids declared int64 but may physically be
// int32 (JAX x64 disabled). If int64 (ids < 2^31), every high word is 0.
// Requires blockDim.x == 256.
__device__ __forceinline__ int detect_shift(const int* __restrict__ tok32,
                                            int* smem_flag) {
    if (threadIdx.x == 0) *smem_flag = 0;
    __syncthreads();
    if (tok32[2 * threadIdx.x + 1] != 0) *smem_flag = 1;
    __syncthreads();
    return *smem_flag ? 0 : 1;
}

// ---------------------------------------------------------------------------
// Kernel 1: fp32->fp16 conversion of X, Wg, Wu  +  routing fused as ONE block.
// grid = (16384, 3):
//   y=0            : X  (16384 blocks x 2048 elems)
//   y=1, x<8192    : Wg
//   y=1, x==8192   : routing block (count -> scan -> perm), runs concurrently
//   y=2, x<8192    : Wu
// Wd conversion happens inside k_mlp<0> (overlapped with the gate+up GEMM).
// ---------------------------------------------------------------------------
__global__ void k_cvt_route(const float* __restrict__ X, const float* __restrict__ Wg,
                            const float* __restrict__ Wu, const int* __restrict__ tok32) {
    const int nW = NE * F_DIM * D_DIM;

    if (blockIdx.y == 1 && blockIdx.x == 8192) {
        // ---- routing: single block, 256 threads ----
        __shared__ int flag;
        __shared__ int hist[NE], fill[NE], poff[NE];
        const int shift = detect_shift(tok32, &flag);
        const int tid = threadIdx.x;
        if (tid < NE) { hist[tid] = 0; fill[tid] = 0; }
        __syncthreads();
        for (int k = tid; k < NT_TOKENS; k += 256)
            atomicAdd(&hist[expert_of_i32(tok32[(size_t)k << shift])], 1);
        __syncthreads();
        if (tid == 0) {
            int acc = 0;
#pragma unroll
            for (int e = 0; e < NE; ++e) {
                poff[e] = acc;
                g_count[e] = hist[e];
                acc += (hist[e] + BM - 1) / BM * BM;
            }
        }
        __syncthreads();
        for (int k = tid; k < NT_TOKENS; k += 256) {
            int e = expert_of_i32(tok32[(size_t)k << shift]);
            g_perm[poff[e] + atomicAdd(&fill[e], 1)] = k;
        }
        return;
    }

    const float* src;
    __half* dst;
    int n;
    switch (blockIdx.y) {
        case 0:  src = X;  dst = hX;  n = NT_TOKENS * D_DIM; break;
        case 1:  src = Wg; dst = hWg; n = nW; break;
        default: src = Wu; dst = hWu; n = nW; break;
    }
    int i = (blockIdx.x * blockDim.x + threadIdx.x) * 8;
    if (i < n) {
        float4 f0 = *(const float4*)(src + i);
        float4 f1 = *(const float4*)(src + i + 4);
        __half2 h[4];
        h[0] = __floats2half2_rn(f0.x, f0.y);
        h[1] = __floats2half2_rn(f0.z, f0.w);
        h[2] = __floats2half2_rn(f1.x, f1.y);
        h[3] = __floats2half2_rn(f1.z, f1.w);
        *(uint4*)(dst + i) = *(uint4*)h;
    }
}

// ---------------------------------------------------------------------------
// PTX helpers (sm_100-baseline legal)
// ---------------------------------------------------------------------------
__device__ __forceinline__ void cpa16(uint32_t s, const void* g) {
    asm volatile("cp.async.cg.shared.global [%0], [%1], 16;" :: "r"(s), "l"(g));
}
__device__ __forceinline__ void cpa_commit() {
    asm volatile("cp.async.commit_group;");
}
template <int N> __device__ __forceinline__ void cpa_wait() {
    asm volatile("cp.async.wait_group %0;" :: "n"(N) : "memory");
}
__device__ __forceinline__ void ldm_x4(uint32_t* r, uint32_t addr) {
    asm volatile("ldmatrix.sync.aligned.m8n8.x4.shared.b16 {%0,%1,%2,%3}, [%4];"
                 : "=r"(r[0]), "=r"(r[1]), "=r"(r[2]), "=r"(r[3]) : "r"(addr));
}
__device__ __forceinline__ void mma16816(float* c, const uint32_t* a,
                                         uint32_t b0, uint32_t b1) {
    asm volatile(
        "mma.sync.aligned.m16n8k16.row.col.f32.f16.f16.f32 "
        "{%0,%1,%2,%3}, {%4,%5,%6,%7}, {%8,%9}, {%0,%1,%2,%3};"
        : "+f"(c[0]), "+f"(c[1]), "+f"(c[2]), "+f"(c[3])
        : "r"(a[0]), "r"(a[1]), "r"(a[2]), "r"(a[3]), "r"(b0), "r"(b1));
}

// ---------------------------------------------------------------------------
// MODE 0 (gate+up fused): CTA tile 128x64, 8 warps 4m x 2n.
//   Extra blocks (blockIdx.x == 32, 132*4 = 528 of them) convert Wd fp32->fp16
//   concurrently with the GEMM (GEMM uses ~3% of DRAM; conversion hides).
// MODE 1 (down+scatter):  CTA tile 128x128, 8 warps 4m x 2n (warp 32x64).
// Both: BK=64 fp16, 3-stage cp.async ring (stage 32KB), SW128 XOR swizzle,
// one __syncthreads per k-tile, 2 CTAs/SM, XOR-folded ldmatrix addressing,
// prefetch issued between ks=0 and ks=1 so cp.async issue overlaps MMAs.
// ---------------------------------------------------------------------------
template <int MODE>
__global__ __launch_bounds__(256, 2)
void k_mlp(float* __restrict__ out, const float* __restrict__ Wd32) {
    constexpr int BN = (MODE == 0) ? 64 : 128;

    if (MODE == 0 && blockIdx.x == F_DIM / 64) {
        // ---- Wd fp32->fp16 conversion (grid-stride over 528 blocks) ----
        const int bid = blockIdx.y * NE + blockIdx.z;          // 0..527
        const size_t stride = (size_t)MT_MAX * NE * 256 * 8;   // 528*256*8
        for (size_t i = ((size_t)bid * 256 + threadIdx.x) * 8;
             i < (size_t)NE * D_DIM * F_DIM; i += stride) {
            float4 f0 = *(const float4*)(Wd32 + i);
            float4 f1 = *(const float4*)(Wd32 + i + 4);
            __half2 h[4];
            h[0] = __floats2half2_rn(f0.x, f0.y);
            h[1] = __floats2half2_rn(f0.z, f0.w);
            h[2] = __floats2half2_rn(f1.x, f1.y);
            h[3] = __floats2half2_rn(f1.z, f1.w);
            *(uint4*)(hWd + i) = *(uint4*)h;
        }
        return;
    }

    const int e   = blockIdx.z;
    const int cnt = g_count[e];
    const int my  = blockIdx.y;
    if (my * BM >= cnt) return;
    const int n0 = blockIdx.x * BN;

    int base = 0;
#pragma unroll
    for (int k = 0; k < NE; ++k)
        if (k < e) base += (g_count[k] + BM - 1) / BM * BM;
    const int rowstart = base + my * BM;

    constexpr int STAGE = 32768;   // MODE0: A16K+Bg8K+Bu8K ; MODE1: A16K+B16K

    extern __shared__ __align__(16) char smem[];
    const uint32_t su = (uint32_t)__cvta_generic_to_shared(smem);

    const int tid = threadIdx.x;
    const int l   = tid & 31;
    const int wid = tid >> 5;
    const int wm  = (wid & 3) * 32;                    // 0,32,64,96
    const int wn  = (wid >> 2) * (BN / 2);             // MODE0: 0/32, MODE1: 0/64

    // ---- cp.async staging: A 4 chunks/thread; B 2 (MODE0: x2 mats) or 4 ----
    const int c = tid & 7;                             // 16B chunk in 128B row
    const char* const baseA = (MODE == 0) ? (const char*)hX : (const char*)hH;
    const char* const baseB1 = (MODE == 0) ? (const char*)hWg : (const char*)hWd;
    const char* const baseB2 = (const char*)hWu;       // MODE0 only

    uint32_t aOff[4];                                  // byte offsets (<4GB)
    uint32_t bOff[4];                                  // MODE0 uses [0..1]
    uint32_t dstA[4];
#pragma unroll
    for (int t = 0; t < 4; ++t) {
        const int row = (tid >> 3) + t * 32;           // 0..127
        dstA[t] = (uint32_t)(row * 128 + ((c ^ (row & 7)) * 16));
        if (MODE == 0) {
            const int grow = (my * BM + row) < cnt ? g_perm[rowstart + row] : 0;
            aOff[t] = (uint32_t)grow * (D_DIM * 2) + c * 16;
        } else {
            aOff[t] = (uint32_t)(rowstart + row) * (F_DIM * 2) + c * 16;
        }
    }
    constexpr int NBCHUNK = (MODE == 0) ? 2 : 4;
#pragma unroll
    for (int t = 0; t < NBCHUNK; ++t) {
        const int row = (tid >> 3) + t * 32;           // 0..BN-1
        bOff[t] = (uint32_t)((size_t)e * F_DIM * D_DIM * 2) +
                  (uint32_t)(n0 + row) * (D_DIM * 2) + c * 16;
    }

#define LOADST(slot, kt)                                                     \
    do {                                                                     \
        const uint32_t sb = su + (uint32_t)(slot) * STAGE;                   \
        const uint32_t ko = (uint32_t)(kt) * 128;                            \
        _Pragma("unroll")                                                    \
        for (int t = 0; t < 4; ++t) cpa16(sb + dstA[t], baseA + aOff[t] + ko);\
        _Pragma("unroll")                                                    \
        for (int t = 0; t < NBCHUNK; ++t) {                                  \
            cpa16(sb + 16384 + dstA[t], baseB1 + bOff[t] + ko);              \
            if (MODE == 0) cpa16(sb + 24576 + dstA[t], baseB2 + bOff[t] + ko);\
        }                                                                    \
        cpa_commit();                                                        \
    } while (0)

    // ---- precomputed ldmatrix fragment constants ----
    const int kha = (l >> 4) & 1;
    const int khb = (l >> 3) & 1;
    uint32_t pA[2];
#pragma unroll
    for (int mi = 0; mi < 2; ++mi) {
        const int r = wm + mi * 16 + (l & 15);
        pA[mi] = (uint32_t)(r * 128 + ((kha ^ (r & 7)) << 4));
    }
    constexpr int NBF = BN / 32;
    uint32_t pB[NBF];
#pragma unroll
    for (int bi = 0; bi < NBF; ++bi) {
        const int r = wn + bi * 16 + ((l & 16) ? 8 : 0) + (l & 7);
        pB[bi] = (uint32_t)(16384 + r * 128 + ((khb ^ (r & 7)) << 4));
    }

    // ---- accumulators ----
    constexpr int NT = BN / 16;
    float c1[2][NT][4];
    float c2[2][NT][4];                                // MODE0 only
#pragma unroll
    for (int mi = 0; mi < 2; ++mi)
#pragma unroll
        for (int nt = 0; nt < NT; ++nt)
#pragma unroll
            for (int k = 0; k < 4; ++k) { c1[mi][nt][k] = 0.f; if (MODE == 0) c2[mi][nt][k] = 0.f; }

    LOADST(0, 0);
    LOADST(1, 1);

    // One MMA sub-step: fragment loads + MMAs for one ks (16-col k slice).
#define KSTEP(ks)                                                            \
    do {                                                                     \
        const uint32_t kx = (uint32_t)((ks) << 5);                           \
        uint32_t a[2][4];                                                    \
        _Pragma("unroll")                                                    \
        for (int mi = 0; mi < 2; ++mi) ldm_x4(a[mi], sbase + (pA[mi] ^ kx)); \
        uint32_t b1[NBF][4];                                                 \
        _Pragma("unroll")                                                    \
        for (int bi = 0; bi < NBF; ++bi) ldm_x4(b1[bi], sbase + (pB[bi] ^ kx));\
        _Pragma("unroll")                                                    \
        for (int mi = 0; mi < 2; ++mi)                                       \
            _Pragma("unroll")                                                \
            for (int nt = 0; nt < NT; ++nt)                                  \
                mma16816(c1[mi][nt], a[mi], b1[nt >> 1][(nt & 1) * 2],       \
                         b1[nt >> 1][(nt & 1) * 2 + 1]);                     \
        if (MODE == 0) {                                                     \
            uint32_t b2[NBF][4];                                             \
            _Pragma("unroll")                                                \
            for (int bi = 0; bi < NBF; ++bi)                                 \
                ldm_x4(b2[bi], sbase + 8192 + (pB[bi] ^ kx));                \
            _Pragma("unroll")                                                \
            for (int mi = 0; mi < 2; ++mi)                                   \
                _Pragma("unroll")                                            \
                for (int nt = 0; nt < NT; ++nt)                              \
                    mma16816(c2[mi][nt], a[mi], b2[nt >> 1][(nt & 1) * 2],   \
                             b2[nt >> 1][(nt & 1) * 2 + 1]);                 \
        }                                                                    \
    } while (0)

    // Single-sync ring: LOADST(kt+2) writes slot (kt-1)%3 whose readers all
    // finished before this iteration's barrier; reads of slot kt%3 are
    // published block-wide by the same barrier.
    for (int kt = 0; kt < KTILES; ++kt) {
        if (kt == KTILES - 1) cpa_wait<0>(); else cpa_wait<1>();
        __syncthreads();
        const uint32_t sbase = su + (uint32_t)(kt % 3) * STAGE;

        KSTEP(0);
        if (kt + 2 < KTILES) LOADST((kt + 2) % 3, kt + 2);
        KSTEP(1);
        KSTEP(2);
        KSTEP(3);
    }
#undef KSTEP

    // ---- epilogue ----
    const int g   = l >> 2;
    const int tig = l & 3;
    const int colbase = n0 + wn + tig * 2;

#pragma unroll
    for (int mi = 0; mi < 2; ++mi) {
#pragma unroll
        for (int h = 0; h < 2; ++h) {
            const int row_local = wm + mi * 16 + h * 8 + g;
            const int p = rowstart + row_local;
            if (MODE == 0) {
                __half* dst = hH + (size_t)p * F_DIM + colbase;
#pragma unroll
                for (int nt = 0; nt < NT; ++nt) {
                    float gv0 = c1[mi][nt][h * 2],     uv0 = c2[mi][nt][h * 2];
                    float gv1 = c1[mi][nt][h * 2 + 1], uv1 = c2[mi][nt][h * 2 + 1];
                    float v0 = (gv0 / (1.0f + __expf(-gv0))) * uv0;
                    float v1 = (gv1 / (1.0f + __expf(-gv1))) * uv1;
                    *(__half2*)(dst + nt * 8) = __floats2half2_rn(v0, v1);
                }
            } else {
                if ((my * BM + row_local) < cnt) {
                    const int tok = g_perm[p];
                    float* dst = out + (size_t)tok * D_DIM + colbase;
#pragma unroll
                    for (int nt = 0; nt < NT; ++nt)
                        *(float2*)(dst + nt * 8) =
                            make_float2(c1[mi][nt][h * 2], c1[mi][nt][h * 2 + 1]);
                }
            }
        }
    }
}

// ---------------------------------------------------------------------------
// Entry.  3 launches: cvt+route, gate+up(+Wd cvt), down+scatter.
// ---------------------------------------------------------------------------
extern "C" void kernel_launch(void* const* d_in, const int* in_sizes, int n_in,
                              void* d_out, int out_size) {
    const float* X     = (const float*)d_in[0];
    const int*   tok32 = (const int*)d_in[1];
    const float* Wg    = (const float*)d_in[2];
    const float* Wu    = (const float*)d_in[3];
    const float* Wd    = (const float*)d_in[4];
    float*       out   = (float*)d_out;

    static bool attr_done = false;
    if (!attr_done) {
        cudaFuncSetAttribute(k_mlp<0>, cudaFuncAttributeMaxDynamicSharedMemorySize, 3 * 32768);
        cudaFuncSetAttribute(k_mlp<1>, cudaFuncAttributeMaxDynamicSharedMemorySize, 3 * 32768);
        attr_done = true;
    }

    // 1: conversion of X/Wg/Wu + fused routing block
    dim3 gcvt(NT_TOKENS * D_DIM / (256 * 8), 3);   // (16384, 3)
    k_cvt_route<<<gcvt, 256>>>(X, Wg, Wu, tok32);

    // 2: gate+up GEMM (CTA 128x64) + concurrent Wd conversion blocks
    dim3 grid0(F_DIM / 64 + 1, MT_MAX, NE);        // (33, 132, 4)
    k_mlp<0><<<grid0, 256, 3 * 32768>>>(nullptr, Wd);

    // 3: down GEMM + fused scatter (CTA 128x128)
    dim3 grid1(D_DIM / 128, MT_MAX, NE);           // (16, 132, 4)
    k_mlp<1><<<grid1, 256, 3 * 32768>>>(out, nullptr);
}